// round 2
// baseline (speedup 1.0000x reference)
#include <cuda_runtime.h>
#include <cstdint>

#define CC 16
#define NN 10000
#define EE 40000
#define FF 256
#define CFGF 18

// ---- scratch (static __device__ arrays; no allocations anywhere) ----
__device__ float g_bufA[CC * NN * FF];   // ping
__device__ float g_bufB[CC * NN * FF];   // pong
__device__ float g_agg [CC * NN * FF];   // scatter-mean accumulator
__device__ float g_base[NN * FF];        // config-independent part of first linear
__device__ float g_T   [CFGF * 8 * FF];  // cfg-embedding x lin_w lookup table
__device__ float g_invdeg[NN];
__device__ float g_pool[CC * FF];

// ---------------------------------------------------------------------
// T[k][v][j] = sum_d emb_layout[v][d] * lin_w[140 + 4k + d][j]
__global__ void k_table(const float* __restrict__ emb_layout,
                        const float* __restrict__ lin_w) {
    int blk = blockIdx.x;            // 0..143
    int k = blk >> 3, v = blk & 7;
    int j = threadIdx.x;
    float acc = 0.f;
#pragma unroll
    for (int d = 0; d < 4; d++)
        acc += emb_layout[v * 4 + d] * lin_w[(140 + k * 4 + d) * FF + j];
    g_T[blk * FF + j] = acc;
}

__global__ void k_deg_zero() {
    int i = blockIdx.x * blockDim.x + threadIdx.x;
    if (i < NN) g_invdeg[i] = 0.f;
}
__global__ void k_deg_acc(const int* __restrict__ edge_index) {
    int e = blockIdx.x * blockDim.x + threadIdx.x;
    if (e < EE) atomicAdd(&g_invdeg[edge_index[EE + e]], 1.0f);
}
__global__ void k_deg_inv() {
    int i = blockIdx.x * blockDim.x + threadIdx.x;
    if (i < NN) g_invdeg[i] = 1.0f / fmaxf(g_invdeg[i], 1.0f);
}

// base[n][j] = lin_b[j] + x_feat[n,:]@lin_w[0:140] + emb_op[x_op[n],:]@lin_w[212:216]
__global__ void k_base(const float* __restrict__ x_feat,
                       const int*   __restrict__ x_op,
                       const float* __restrict__ emb_op,
                       const float* __restrict__ lin_w,
                       const float* __restrict__ lin_b) {
    int n = blockIdx.x;
    int j = threadIdx.x;
    __shared__ float sf[144];
    if (j < 140) sf[j] = x_feat[n * 140 + j];
    if (j >= 140 && j < 144) {
        int op = x_op[n];
        sf[j] = emb_op[op * 4 + (j - 140)];
    }
    __syncthreads();
    float acc = lin_b[j];
#pragma unroll 4
    for (int d = 0; d < 140; d++) acc += sf[d] * lin_w[d * FF + j];
#pragma unroll
    for (int d = 0; d < 4; d++)   acc += sf[140 + d] * lin_w[(212 + d) * FF + j];
    g_base[n * FF + j] = acc;
}

// x[c][n][j] = base[n][j] + sum_k T[k][cfg[c,n,k]][j]
__global__ void k_initx(const int* __restrict__ x_node_cfg) {
    int n = blockIdx.x, c = blockIdx.y, j = threadIdx.x;
    __shared__ int scfg[CFGF];
    if (j < CFGF) scfg[j] = x_node_cfg[((size_t)c * NN + n) * CFGF + j];
    __syncthreads();
    float acc = g_base[n * FF + j];
#pragma unroll
    for (int k = 0; k < CFGF; k++)
        acc += g_T[(k * 8 + scfg[k]) * FF + j];
    g_bufA[((size_t)c * NN + n) * FF + j] = acc;
}

__global__ void k_zero_agg() {
    size_t i = (size_t)blockIdx.x * blockDim.x + threadIdx.x;  // CC*NN*FF/4 threads
    ((float4*)g_agg)[i] = make_float4(0.f, 0.f, 0.f, 0.f);
}

// scatter: agg[c][dst][:] += x[c][src][:]
__global__ void k_agg(int srcA, const int* __restrict__ edge_index) {
    const float* __restrict__ x = srcA ? g_bufA : g_bufB;
    int e = blockIdx.x;
    int j = threadIdx.x;
    int src = edge_index[e];
    int dst = edge_index[EE + e];
    const float* xs = x + (size_t)src * FF + j;
    float*       ad = g_agg + (size_t)dst * FF + j;
#pragma unroll
    for (int c = 0; c < CC; c++)
        atomicAdd(ad + (size_t)c * NN * FF, xs[(size_t)c * NN * FF]);
}

// fused conv GEMM:  out = relu( [agg*invdeg | x](M x 512) @ [wl ; wr](512 x 256) + bl )
// tiles: 128x128, BK=16, 256 threads, 8x8 per thread
__global__ __launch_bounds__(256) void k_conv(int srcA,
    const float* __restrict__ wl, const float* __restrict__ wr,
    const float* __restrict__ bl)
{
    const float* __restrict__ x   = srcA ? g_bufA : g_bufB;
    float*       __restrict__ out = srcA ? g_bufB : g_bufA;

    __shared__ float As[16][132];
    __shared__ float Bs[16][128];

    const int tid  = threadIdx.x;
    const int row0 = blockIdx.x * 128;
    const int col0 = blockIdx.y * 128;

    const int lr = tid >> 2;            // 0..63
    const int lk = (tid & 3) << 2;      // 0,4,8,12
    const int R0 = row0 + lr;
    const int R1 = R0 + 64;
    const float inv0 = g_invdeg[R0 % NN];
    const float inv1 = g_invdeg[R1 % NN];

    const int bk = tid >> 5;            // 0..7
    const int bc = (tid & 31) << 2;     // 0..124

    const int tr = (tid >> 4) << 3;     // 0..120
    const int tc = (tid & 15) << 3;     // 0..120

    float acc[8][8];
#pragma unroll
    for (int i = 0; i < 8; i++)
#pragma unroll
        for (int j = 0; j < 8; j++) acc[i][j] = 0.f;

    for (int kt = 0; kt < 32; kt++) {
        float4 a0, a1, b0, b1;
        if (kt < 16) {
            const int kg = kt * 16 + lk;
            a0 = *(const float4*)(g_agg + (size_t)R0 * FF + kg);
            a1 = *(const float4*)(g_agg + (size_t)R1 * FF + kg);
            a0.x *= inv0; a0.y *= inv0; a0.z *= inv0; a0.w *= inv0;
            a1.x *= inv1; a1.y *= inv1; a1.z *= inv1; a1.w *= inv1;
            const int kb = kt * 16 + bk;
            b0 = *(const float4*)(wl + kb * FF + col0 + bc);
            b1 = *(const float4*)(wl + (kb + 8) * FF + col0 + bc);
        } else {
            const int kg = (kt - 16) * 16 + lk;
            a0 = *(const float4*)(x + (size_t)R0 * FF + kg);
            a1 = *(const float4*)(x + (size_t)R1 * FF + kg);
            const int kb = (kt - 16) * 16 + bk;
            b0 = *(const float4*)(wr + kb * FF + col0 + bc);
            b1 = *(const float4*)(wr + (kb + 8) * FF + col0 + bc);
        }
        __syncthreads();
        As[lk + 0][lr]      = a0.x; As[lk + 1][lr]      = a0.y;
        As[lk + 2][lr]      = a0.z; As[lk + 3][lr]      = a0.w;
        As[lk + 0][64 + lr] = a1.x; As[lk + 1][64 + lr] = a1.y;
        As[lk + 2][64 + lr] = a1.z; As[lk + 3][64 + lr] = a1.w;
        *(float4*)(&Bs[bk][bc])     = b0;
        *(float4*)(&Bs[bk + 8][bc]) = b1;
        __syncthreads();
#pragma unroll
        for (int k = 0; k < 16; k++) {
            float a[8], b[8];
            *(float4*)(a)     = *(const float4*)(&As[k][tr]);
            *(float4*)(a + 4) = *(const float4*)(&As[k][tr + 4]);
            *(float4*)(b)     = *(const float4*)(&Bs[k][tc]);
            *(float4*)(b + 4) = *(const float4*)(&Bs[k][tc + 4]);
#pragma unroll
            for (int i = 0; i < 8; i++)
#pragma unroll
                for (int j = 0; j < 8; j++)
                    acc[i][j] += a[i] * b[j];
        }
    }

    float bj[8];
#pragma unroll
    for (int j = 0; j < 8; j++) bj[j] = bl[col0 + tc + j];
#pragma unroll
    for (int i = 0; i < 8; i++) {
        const size_t o = (size_t)(row0 + tr + i) * FF + col0 + tc;
        float4 v0, v1;
        v0.x = fmaxf(acc[i][0] + bj[0], 0.f);
        v0.y = fmaxf(acc[i][1] + bj[1], 0.f);
        v0.z = fmaxf(acc[i][2] + bj[2], 0.f);
        v0.w = fmaxf(acc[i][3] + bj[3], 0.f);
        v1.x = fmaxf(acc[i][4] + bj[4], 0.f);
        v1.y = fmaxf(acc[i][5] + bj[5], 0.f);
        v1.z = fmaxf(acc[i][6] + bj[6], 0.f);
        v1.w = fmaxf(acc[i][7] + bj[7], 0.f);
        *(float4*)(out + o)     = v0;
        *(float4*)(out + o + 4) = v1;
    }
}

__global__ void k_pool_zero() {
    int i = blockIdx.x * blockDim.x + threadIdx.x;
    if (i < CC * FF) g_pool[i] = 0.f;
}
// pool partial sums: block (c, chunk) handles 250 nodes
__global__ void k_pool() {
    int c = blockIdx.x, chunk = blockIdx.y, j = threadIdx.x;
    int n0 = chunk * 250;
    float acc = 0.f;
    for (int n = n0; n < n0 + 250; n++)
        acc += g_bufA[((size_t)c * NN + n) * FF + j];
    atomicAdd(&g_pool[c * FF + j], acc);
}

// whole MLP in one block
__global__ __launch_bounds__(256) void k_mlp(
    const float* __restrict__ w1, const float* __restrict__ b1,
    const float* __restrict__ w2, const float* __restrict__ b2,
    const float* __restrict__ w3, const float* __restrict__ b3,
    float* __restrict__ outp)
{
    __shared__ float g[CC][FF];
    __shared__ float h[CC][FF];
    int j = threadIdx.x;
    const float scale = 1.0f / (float)NN;
#pragma unroll
    for (int c = 0; c < CC; c++) g[c][j] = g_pool[c * FF + j] * scale;
    __syncthreads();

    // h = relu(g @ w1 + b1)
    {
        float accs[CC];
#pragma unroll
        for (int c = 0; c < CC; c++) accs[c] = 0.f;
        for (int k = 0; k < FF; k++) {
            float wv = w1[k * FF + j];
#pragma unroll
            for (int c = 0; c < CC; c++) accs[c] += g[c][k] * wv;
        }
        float bb = b1[j];
#pragma unroll
        for (int c = 0; c < CC; c++) h[c][j] = fmaxf(accs[c] + bb, 0.f);
    }
    __syncthreads();

    // g = relu(h @ w2 + b2)
    {
        float accs[CC];
#pragma unroll
        for (int c = 0; c < CC; c++) accs[c] = 0.f;
        for (int k = 0; k < FF; k++) {
            float wv = w2[k * FF + j];
#pragma unroll
            for (int c = 0; c < CC; c++) accs[c] += h[c][k] * wv;
        }
        float bb = b2[j];
#pragma unroll
        for (int c = 0; c < CC; c++) g[c][j] = fmaxf(accs[c] + bb, 0.f);
    }
    __syncthreads();

    // out[c] = g[c,:] @ w3 + b3
    {
        float wv = w3[j];
#pragma unroll
        for (int c = 0; c < CC; c++) h[c][j] = g[c][j] * wv;
        __syncthreads();
        if (j < CC) {
            float s = 0.f;
            for (int k = 0; k < FF; k++) s += h[j][k];
            outp[j] = s + b3[0];
        }
    }
}

// ---------------------------------------------------------------------
extern "C" void kernel_launch(void* const* d_in, const int* in_sizes, int n_in,
                              void* d_out, int out_size) {
    const int*   x_node_cfg = (const int*)  d_in[0];
    const float* x_feat     = (const float*)d_in[1];
    const int*   x_op       = (const int*)  d_in[2];
    const int*   edge_index = (const int*)  d_in[3];
    const float* emb_op     = (const float*)d_in[4];
    const float* emb_layout = (const float*)d_in[5];
    const float* lin_w      = (const float*)d_in[6];
    const float* lin_b      = (const float*)d_in[7];
    const float* conv_wl    = (const float*)d_in[8];
    const float* conv_bl    = (const float*)d_in[9];
    const float* conv_wr    = (const float*)d_in[10];
    const float* w1         = (const float*)d_in[11];
    const float* b1         = (const float*)d_in[12];
    const float* w2         = (const float*)d_in[13];
    const float* b2         = (const float*)d_in[14];
    const float* w3         = (const float*)d_in[15];
    const float* b3         = (const float*)d_in[16];
    float* outp = (float*)d_out;

    k_table<<<CFGF * 8, FF>>>(emb_layout, lin_w);
    k_deg_zero<<<(NN + 255) / 256, 256>>>();
    k_deg_acc<<<(EE + 255) / 256, 256>>>(edge_index);
    k_deg_inv<<<(NN + 255) / 256, 256>>>();
    k_base<<<NN, FF>>>(x_feat, x_op, emb_op, lin_w, lin_b);
    k_initx<<<dim3(NN, CC), FF>>>(x_node_cfg);

    for (int i = 0; i < 4; i++) {
        int srcA = (i % 2 == 0) ? 1 : 0;
        k_zero_agg<<<(CC * NN * FF / 4 + 255) / 256, 256>>>();
        k_agg<<<EE, FF>>>(srcA, edge_index);
        k_conv<<<dim3((CC * NN) / 128, FF / 128), 256>>>(
            srcA, conv_wl + (size_t)i * FF * FF, conv_wr + (size_t)i * FF * FF,
            conv_bl + (size_t)i * FF);
    }

    k_pool_zero<<<(CC * FF + 255) / 256, 256>>>();
    k_pool<<<dim3(CC, NN / 250), FF>>>();
    k_mlp<<<1, FF>>>(w1, b1, w2, b2, w3, b3, outp);
}

// round 3
// speedup vs baseline: 1.1840x; 1.1840x over previous
#include <cuda_runtime.h>
#include <cstdint>

#define CC 16
#define NN 10000
#define EE 40000
#define FF 256
#define CFGF 18

// ---- scratch (static __device__ arrays; no allocations anywhere) ----
__device__ float g_bufA[CC * NN * FF];   // ping (x)
__device__ float g_bufB[CC * NN * FF];   // pong (x)
__device__ float g_yl [CC * NN * FF];    // x @ wl
__device__ float g_yr [CC * NN * FF];    // x @ wr + bl
__device__ float g_base[NN * FF];
__device__ float g_T   [CFGF * 8 * FF];
__device__ float g_invdeg[NN];
__device__ float g_pool[CC * FF];
__device__ int   g_deg[NN];
__device__ int   g_cursor[NN];
__device__ int   g_rowptr[NN + 1];
__device__ int   g_colidx[EE];

// ---------------------------------------------------------------------
__global__ void k_table(const float* __restrict__ emb_layout,
                        const float* __restrict__ lin_w) {
    int blk = blockIdx.x;            // 0..143
    int k = blk >> 3, v = blk & 7;
    int j = threadIdx.x;
    float acc = 0.f;
#pragma unroll
    for (int d = 0; d < 4; d++)
        acc += emb_layout[v * 4 + d] * lin_w[(140 + k * 4 + d) * FF + j];
    g_T[blk * FF + j] = acc;
}

__global__ void k_small_zero() {
    int i = blockIdx.x * blockDim.x + threadIdx.x;
    if (i < NN) { g_deg[i] = 0; g_cursor[i] = 0; }
    if (i < CC * FF) g_pool[i] = 0.f;
}
__global__ void k_deg_acc(const int* __restrict__ edge_index) {
    int e = blockIdx.x * blockDim.x + threadIdx.x;
    if (e < EE) atomicAdd(&g_deg[edge_index[EE + e]], 1);
}
// single-block prefix scan over NN degrees -> row_ptr, inv_deg
__global__ void k_scan() {
    __shared__ int csum[256];
    int t = threadIdx.x;
    const int CH = (NN + 255) / 256;  // 40
    int base = t * CH;
    int s = 0;
    for (int i = 0; i < CH; i++) {
        int idx = base + i;
        if (idx < NN) s += g_deg[idx];
    }
    csum[t] = s;
    __syncthreads();
    if (t == 0) {
        int acc = 0;
        for (int i = 0; i < 256; i++) { int v = csum[i]; csum[i] = acc; acc += v; }
        g_rowptr[NN] = acc;
    }
    __syncthreads();
    int acc = csum[t];
    for (int i = 0; i < CH; i++) {
        int idx = base + i;
        if (idx < NN) {
            g_rowptr[idx] = acc;
            int d = g_deg[idx];
            acc += d;
            g_invdeg[idx] = 1.0f / fmaxf((float)d, 1.0f);
        }
    }
}
__global__ void k_fill(const int* __restrict__ edge_index) {
    int e = blockIdx.x * blockDim.x + threadIdx.x;
    if (e < EE) {
        int dst = edge_index[EE + e];
        int p = atomicAdd(&g_cursor[dst], 1);
        g_colidx[g_rowptr[dst] + p] = edge_index[e];
    }
}

__global__ void k_base(const float* __restrict__ x_feat,
                       const int*   __restrict__ x_op,
                       const float* __restrict__ emb_op,
                       const float* __restrict__ lin_w,
                       const float* __restrict__ lin_b) {
    int n = blockIdx.x;
    int j = threadIdx.x;
    __shared__ float sf[144];
    if (j < 140) sf[j] = x_feat[n * 140 + j];
    if (j >= 140 && j < 144) {
        int op = x_op[n];
        sf[j] = emb_op[op * 4 + (j - 140)];
    }
    __syncthreads();
    float acc = lin_b[j];
#pragma unroll 4
    for (int d = 0; d < 140; d++) acc += sf[d] * lin_w[d * FF + j];
#pragma unroll
    for (int d = 0; d < 4; d++)   acc += sf[140 + d] * lin_w[(212 + d) * FF + j];
    g_base[n * FF + j] = acc;
}

__global__ void k_initx(const int* __restrict__ x_node_cfg) {
    int n = blockIdx.x, c = blockIdx.y, j = threadIdx.x;
    __shared__ int scfg[CFGF];
    if (j < CFGF) scfg[j] = x_node_cfg[((size_t)c * NN + n) * CFGF + j];
    __syncthreads();
    float acc = g_base[n * FF + j];
#pragma unroll
    for (int k = 0; k < CFGF; k++)
        acc += g_T[(k * 8 + scfg[k]) * FF + j];
    g_bufA[((size_t)c * NN + n) * FF + j] = acc;
}

// GEMM: y = x @ [wl | wr]   (M=CC*NN, K=256, N=512), f32x2 packed FMA
__global__ __launch_bounds__(256, 2) void k_gemm(int srcA,
    const float* __restrict__ wl, const float* __restrict__ wr,
    const float* __restrict__ bl)
{
    const float* __restrict__ x = srcA ? g_bufA : g_bufB;

    __shared__ float As[16][132];
    __shared__ float Bs[16][128];

    const int tid  = threadIdx.x;
    const int col0 = blockIdx.x * 128;       // 0..384
    const int row0 = blockIdx.y * 128;

    const float* __restrict__ w = (col0 < 256) ? wl : wr;
    const int wc = col0 & 255;

    const int lr = tid >> 2;            // 0..63
    const int lk = (tid & 3) << 2;      // 0,4,8,12
    const int R0 = row0 + lr;
    const int R1 = R0 + 64;

    const int bk = tid >> 5;            // 0..7
    const int bc = (tid & 31) << 2;     // 0..124

    const int tr = (tid >> 4) << 3;     // 0..120
    const int tc = (tid & 15) << 3;     // 0..120

    unsigned long long acc2[8][4];
#pragma unroll
    for (int i = 0; i < 8; i++)
#pragma unroll
        for (int jj = 0; jj < 4; jj++) acc2[i][jj] = 0ull;

    for (int kt = 0; kt < 16; kt++) {
        const int kg = kt * 16 + lk;
        float4 a0 = *(const float4*)(x + (size_t)R0 * FF + kg);
        float4 a1 = *(const float4*)(x + (size_t)R1 * FF + kg);
        const int kb = kt * 16 + bk;
        float4 b0 = *(const float4*)(w + kb * FF + wc + bc);
        float4 b1 = *(const float4*)(w + (kb + 8) * FF + wc + bc);
        __syncthreads();
        As[lk + 0][lr]      = a0.x; As[lk + 1][lr]      = a0.y;
        As[lk + 2][lr]      = a0.z; As[lk + 3][lr]      = a0.w;
        As[lk + 0][64 + lr] = a1.x; As[lk + 1][64 + lr] = a1.y;
        As[lk + 2][64 + lr] = a1.z; As[lk + 3][64 + lr] = a1.w;
        *(float4*)(&Bs[bk][bc])     = b0;
        *(float4*)(&Bs[bk + 8][bc]) = b1;
        __syncthreads();
#pragma unroll
        for (int k = 0; k < 16; k++) {
            float a[8];
            *(float4*)(a)     = *(const float4*)(&As[k][tr]);
            *(float4*)(a + 4) = *(const float4*)(&As[k][tr + 4]);
            unsigned long long b2[4];
#pragma unroll
            for (int jj = 0; jj < 4; jj++)
                b2[jj] = *(const unsigned long long*)(&Bs[k][tc + 2 * jj]);
#pragma unroll
            for (int i = 0; i < 8; i++) {
                unsigned long long a2;
                asm("mov.b64 %0, {%1, %1};" : "=l"(a2) : "r"(__float_as_uint(a[i])));
#pragma unroll
                for (int jj = 0; jj < 4; jj++)
                    asm("fma.rn.f32x2 %0, %1, %2, %0;"
                        : "+l"(acc2[i][jj]) : "l"(a2), "l"(b2[jj]));
            }
        }
    }

    if (col0 < 256) {
#pragma unroll
        for (int i = 0; i < 8; i++) {
            unsigned long long* o =
                (unsigned long long*)(g_yl + (size_t)(row0 + tr + i) * FF + col0 + tc);
#pragma unroll
            for (int jj = 0; jj < 4; jj++) o[jj] = acc2[i][jj];
        }
    } else {
        float bj[8];
#pragma unroll
        for (int j = 0; j < 8; j++) bj[j] = bl[wc + tc + j];
#pragma unroll
        for (int i = 0; i < 8; i++) {
            float o[8];
#pragma unroll
            for (int jj = 0; jj < 4; jj++) {
                unsigned int lo, hi;
                asm("mov.b64 {%0, %1}, %2;" : "=r"(lo), "=r"(hi) : "l"(acc2[i][jj]));
                o[2 * jj]     = __uint_as_float(lo) + bj[2 * jj];
                o[2 * jj + 1] = __uint_as_float(hi) + bj[2 * jj + 1];
            }
            float* op = g_yr + (size_t)(row0 + tr + i) * FF + wc + tc;
            *(float4*)(op)     = *(float4*)(o);
            *(float4*)(op + 4) = *(float4*)(o + 4);
        }
    }
}

// out[c][n][j] = relu( invdeg[n] * sum_{src in N(n)} yl[c][src][j] + yr[c][n][j] )
__global__ __launch_bounds__(256) void k_sage(int dstA) {
    float* __restrict__ out = dstA ? g_bufA : g_bufB;
    int n = blockIdx.x;
    int j = threadIdx.x;
    int e0 = g_rowptr[n], e1 = g_rowptr[n + 1];
    float inv = g_invdeg[n];

    float sacc[CC];
#pragma unroll
    for (int c = 0; c < CC; c++) sacc[c] = 0.f;

    __shared__ int sc[64];
    for (int eb = e0; eb < e1; eb += 64) {
        int m = min(64, e1 - eb);
        __syncthreads();
        if (j < m) sc[j] = g_colidx[eb + j];
        __syncthreads();
        for (int q = 0; q < m; q++) {
            int src = sc[q];
            const float* p = g_yl + (size_t)src * FF + j;
#pragma unroll
            for (int c = 0; c < CC; c++)
                sacc[c] += p[(size_t)c * NN * FF];
        }
    }
#pragma unroll
    for (int c = 0; c < CC; c++) {
        size_t o = ((size_t)c * NN + n) * FF + j;
        out[o] = fmaxf(sacc[c] * inv + g_yr[o], 0.f);
    }
}

__global__ void k_pool() {
    int c = blockIdx.x, chunk = blockIdx.y, j = threadIdx.x;
    int n0 = chunk * 250;
    float acc = 0.f;
    for (int n = n0; n < n0 + 250; n++)
        acc += g_bufA[((size_t)c * NN + n) * FF + j];
    atomicAdd(&g_pool[c * FF + j], acc);
}

__global__ __launch_bounds__(256) void k_mlp(
    const float* __restrict__ w1, const float* __restrict__ b1,
    const float* __restrict__ w2, const float* __restrict__ b2,
    const float* __restrict__ w3, const float* __restrict__ b3,
    float* __restrict__ outp)
{
    __shared__ float g[CC][FF];
    __shared__ float h[CC][FF];
    int j = threadIdx.x;
    const float scale = 1.0f / (float)NN;
#pragma unroll
    for (int c = 0; c < CC; c++) g[c][j] = g_pool[c * FF + j] * scale;
    __syncthreads();
    {
        float accs[CC];
#pragma unroll
        for (int c = 0; c < CC; c++) accs[c] = 0.f;
        for (int k = 0; k < FF; k++) {
            float wv = w1[k * FF + j];
#pragma unroll
            for (int c = 0; c < CC; c++) accs[c] += g[c][k] * wv;
        }
        float bb = b1[j];
#pragma unroll
        for (int c = 0; c < CC; c++) h[c][j] = fmaxf(accs[c] + bb, 0.f);
    }
    __syncthreads();
    {
        float accs[CC];
#pragma unroll
        for (int c = 0; c < CC; c++) accs[c] = 0.f;
        for (int k = 0; k < FF; k++) {
            float wv = w2[k * FF + j];
#pragma unroll
            for (int c = 0; c < CC; c++) accs[c] += h[c][k] * wv;
        }
        float bb = b2[j];
#pragma unroll
        for (int c = 0; c < CC; c++) g[c][j] = fmaxf(accs[c] + bb, 0.f);
    }
    __syncthreads();
    {
        float wv = w3[j];
#pragma unroll
        for (int c = 0; c < CC; c++) h[c][j] = g[c][j] * wv;
        __syncthreads();
        if (j < CC) {
            float s = 0.f;
            for (int k = 0; k < FF; k++) s += h[j][k];
            outp[j] = s + b3[0];
        }
    }
}

// ---------------------------------------------------------------------
extern "C" void kernel_launch(void* const* d_in, const int* in_sizes, int n_in,
                              void* d_out, int out_size) {
    const int*   x_node_cfg = (const int*)  d_in[0];
    const float* x_feat     = (const float*)d_in[1];
    const int*   x_op       = (const int*)  d_in[2];
    const int*   edge_index = (const int*)  d_in[3];
    const float* emb_op     = (const float*)d_in[4];
    const float* emb_layout = (const float*)d_in[5];
    const float* lin_w      = (const float*)d_in[6];
    const float* lin_b      = (const float*)d_in[7];
    const float* conv_wl    = (const float*)d_in[8];
    const float* conv_bl    = (const float*)d_in[9];
    const float* conv_wr    = (const float*)d_in[10];
    const float* w1         = (const float*)d_in[11];
    const float* b1         = (const float*)d_in[12];
    const float* w2         = (const float*)d_in[13];
    const float* b2         = (const float*)d_in[14];
    const float* w3         = (const float*)d_in[15];
    const float* b3         = (const float*)d_in[16];
    float* outp = (float*)d_out;

    k_table<<<CFGF * 8, FF>>>(emb_layout, lin_w);
    k_small_zero<<<(NN + 255) / 256, 256>>>();
    k_deg_acc<<<(EE + 255) / 256, 256>>>(edge_index);
    k_scan<<<1, 256>>>();
    k_fill<<<(EE + 255) / 256, 256>>>(edge_index);
    k_base<<<NN, FF>>>(x_feat, x_op, emb_op, lin_w, lin_b);
    k_initx<<<dim3(NN, CC), FF>>>(x_node_cfg);

    for (int i = 0; i < 4; i++) {
        int srcA = (i % 2 == 0) ? 1 : 0;
        k_gemm<<<dim3(4, (CC * NN) / 128), 256>>>(srcA,
            conv_wl + (size_t)i * FF * FF, conv_wr + (size_t)i * FF * FF,
            conv_bl + (size_t)i * FF);
        k_sage<<<NN, FF>>>(srcA ? 0 : 1);
    }

    k_pool<<<dim3(CC, NN / 250), FF>>>();
    k_mlp<<<1, FF>>>(w1, b1, w2, b2, w3, b3, outp);
}

// round 6
// speedup vs baseline: 1.5149x; 1.2795x over previous
#include <cuda_runtime.h>
#include <cuda_bf16.h>
#include <cstdint>

#define CC 16
#define NN 10000
#define EE 40000
#define FF 256
#define CFGF 18

// ---- scratch (static __device__ arrays; no allocations anywhere) ----
__device__ float g_bufA[CC * NN * FF];   // ping (x)
__device__ float g_bufB[CC * NN * FF];   // pong (x)
__device__ float g_yl [CC * NN * FF];    // x @ wl
__device__ float g_yr [CC * NN * FF];    // x @ wr + bl
__device__ float g_base[NN * FF];
__device__ float g_T   [CFGF * 8 * FF];
__device__ float g_invdeg[NN];
__device__ float g_pool[CC * FF];
__device__ int   g_deg[NN];
__device__ int   g_cursor[NN];
__device__ int   g_rowptr[NN + 1];
__device__ int   g_colidx[EE];
__device__ __nv_bfloat16 g_whi[4 * 512 * 256];  // weights split hi, [layer][n][k]
__device__ __nv_bfloat16 g_wlo[4 * 512 * 256];  // weights split lo

// ================= helpers =================
#define SWZ(o) ((o) ^ (((o) >> 3) & 0x70))

__device__ __forceinline__ uint32_t s2u(const void* p) {
    uint32_t a;
    asm("{ .reg .u64 t; cvta.to.shared.u64 t, %1; cvt.u32.u64 %0, t; }"
        : "=r"(a) : "l"(p));
    return a;
}
__device__ __forceinline__ void ldm_x4(uint32_t* r, uint32_t addr) {
    asm volatile("ldmatrix.sync.aligned.m8n8.x4.shared.b16 {%0,%1,%2,%3}, [%4];"
                 : "=r"(r[0]), "=r"(r[1]), "=r"(r[2]), "=r"(r[3]) : "r"(addr));
}
__device__ __forceinline__ void ldm_x2(uint32_t* r, uint32_t addr) {
    asm volatile("ldmatrix.sync.aligned.m8n8.x2.shared.b16 {%0,%1}, [%2];"
                 : "=r"(r[0]), "=r"(r[1]) : "r"(addr));
}
__device__ __forceinline__ void mma16816(float* d, const uint32_t* a, const uint32_t* b) {
    asm volatile(
        "mma.sync.aligned.m16n8k16.row.col.f32.bf16.bf16.f32 "
        "{%0,%1,%2,%3}, {%4,%5,%6,%7}, {%8,%9}, {%0,%1,%2,%3};"
        : "+f"(d[0]), "+f"(d[1]), "+f"(d[2]), "+f"(d[3])
        : "r"(a[0]), "r"(a[1]), "r"(a[2]), "r"(a[3]), "r"(b[0]), "r"(b[1]));
}

// ================= prologue kernels =================
__global__ void k_table(const float* __restrict__ emb_layout,
                        const float* __restrict__ lin_w) {
    int blk = blockIdx.x;            // 0..143
    int k = blk >> 3, v = blk & 7;
    int j = threadIdx.x;
    float acc = 0.f;
#pragma unroll
    for (int d = 0; d < 4; d++)
        acc += emb_layout[v * 4 + d] * lin_w[(140 + k * 4 + d) * FF + j];
    g_T[blk * FF + j] = acc;
}

__global__ void k_small_zero() {
    int i = blockIdx.x * blockDim.x + threadIdx.x;
    if (i < NN) { g_deg[i] = 0; g_cursor[i] = 0; }
    if (i < CC * FF) g_pool[i] = 0.f;
}
__global__ void k_deg_acc(const int* __restrict__ edge_index) {
    int e = blockIdx.x * blockDim.x + threadIdx.x;
    if (e < EE) atomicAdd(&g_deg[edge_index[EE + e]], 1);
}
__global__ void k_scan() {
    __shared__ int csum[256];
    int t = threadIdx.x;
    const int CH = (NN + 255) / 256;  // 40
    int base = t * CH;
    int s = 0;
    for (int i = 0; i < CH; i++) {
        int idx = base + i;
        if (idx < NN) s += g_deg[idx];
    }
    csum[t] = s;
    __syncthreads();
    if (t == 0) {
        int acc = 0;
        for (int i = 0; i < 256; i++) { int v = csum[i]; csum[i] = acc; acc += v; }
        g_rowptr[NN] = acc;
    }
    __syncthreads();
    int acc = csum[t];
    for (int i = 0; i < CH; i++) {
        int idx = base + i;
        if (idx < NN) {
            g_rowptr[idx] = acc;
            int d = g_deg[idx];
            acc += d;
            g_invdeg[idx] = 1.0f / fmaxf((float)d, 1.0f);
        }
    }
}
__global__ void k_fill(const int* __restrict__ edge_index) {
    int e = blockIdx.x * blockDim.x + threadIdx.x;
    if (e < EE) {
        int dst = edge_index[EE + e];
        int p = atomicAdd(&g_cursor[dst], 1);
        g_colidx[g_rowptr[dst] + p] = edge_index[e];
    }
}

__global__ void k_base(const float* __restrict__ x_feat,
                       const int*   __restrict__ x_op,
                       const float* __restrict__ emb_op,
                       const float* __restrict__ lin_w,
                       const float* __restrict__ lin_b) {
    int n = blockIdx.x;
    int j = threadIdx.x;
    __shared__ float sf[144];
    if (j < 140) sf[j] = x_feat[n * 140 + j];
    if (j >= 140 && j < 144) {
        int op = x_op[n];
        sf[j] = emb_op[op * 4 + (j - 140)];
    }
    __syncthreads();
    float acc = lin_b[j];
#pragma unroll 4
    for (int d = 0; d < 140; d++) acc += sf[d] * lin_w[d * FF + j];
#pragma unroll
    for (int d = 0; d < 4; d++)   acc += sf[140 + d] * lin_w[(212 + d) * FF + j];
    g_base[n * FF + j] = acc;
}

__global__ void k_initx(const int* __restrict__ x_node_cfg) {
    int n = blockIdx.x, c = blockIdx.y, j = threadIdx.x;
    __shared__ int scfg[CFGF];
    if (j < CFGF) scfg[j] = x_node_cfg[((size_t)c * NN + n) * CFGF + j];
    __syncthreads();
    float acc = g_base[n * FF + j];
#pragma unroll
    for (int k = 0; k < CFGF; k++)
        acc += g_T[(k * 8 + scfg[k]) * FF + j];
    g_bufA[((size_t)c * NN + n) * FF + j] = acc;
}

// split all 4 layers' weights into bf16 hi/lo in [layer][n(512)][k(256)] layout
__global__ void k_wsplit(const float* __restrict__ conv_wl,
                         const float* __restrict__ conv_wr) {
    int t = blockIdx.x * 256 + threadIdx.x;   // 0 .. 4*512*256-1
    int l = t >> 17;
    int rem = t & 131071;
    int n = rem >> 8, k = rem & 255;
    const float* w = (n < 256) ? (conv_wl + (size_t)l * 65536)
                               : (conv_wr + (size_t)l * 65536);
    float v = w[k * 256 + (n & 255)];
    __nv_bfloat16 h = __float2bfloat16(v);
    g_whi[t] = h;
    g_wlo[t] = __float2bfloat16(v - __bfloat162float(h));
}

// ================= HMMA bf16x3 GEMM =================
// y = x @ [wl | wr]  (M=160000, K=256, N=512)
// CTA 128x128; grid (4 col tiles, 1250 row tiles); 8 warps: 2(m) x 4(n)
// smem: A_hi 16K | A_lo 16K | B_hi 16K | B_lo 16K  = 64KB  (chunk K=64)
__global__ __launch_bounds__(256) void k_gemm_mma(int srcA, int layer,
                                                  const float* __restrict__ bl) {
    extern __shared__ __align__(128) char smem[];
    const float* __restrict__ x = srcA ? g_bufA : g_bufB;

    const int tid = threadIdx.x;
    const int wid = tid >> 5, lane = tid & 31;
    const int col0 = blockIdx.x * 128;
    const int m0 = blockIdx.y * 128;
    const int wm = (wid & 1) * 64;       // warp m base
    const int wn = (wid >> 1) * 32;      // warp n base

    const uint32_t sA_hi = s2u(smem);
    const uint32_t sA_lo = sA_hi + 16384;
    const uint32_t sB_hi = sA_hi + 32768;
    const uint32_t sB_lo = sA_hi + 49152;

    float acc[4][4][4];
#pragma unroll
    for (int i = 0; i < 4; i++)
#pragma unroll
        for (int j = 0; j < 4; j++)
#pragma unroll
            for (int q = 0; q < 4; q++) acc[i][j][q] = 0.f;

    const int r = tid >> 1, half = tid & 1;
    const float* ap = x + (size_t)(m0 + r) * FF + half * 32;
    const __nv_bfloat16* bhp = g_whi + ((size_t)(layer * 512 + col0 + r) << 8) + half * 32;
    const __nv_bfloat16* blp = g_wlo + ((size_t)(layer * 512 + col0 + r) << 8) + half * 32;

    for (int kc = 0; kc < 4; kc++) {
        __syncthreads();
        // ---- A chunk: load fp32, split to bf16 hi/lo, store swizzled ----
#pragma unroll
        for (int i = 0; i < 8; i++) {
            float4 v = *(const float4*)(ap + kc * 64 + i * 4);
            __nv_bfloat16 h0 = __float2bfloat16(v.x), h1 = __float2bfloat16(v.y),
                          h2 = __float2bfloat16(v.z), h3 = __float2bfloat16(v.w);
            __nv_bfloat162 hp0; hp0.x = h0; hp0.y = h1;
            __nv_bfloat162 hp1; hp1.x = h2; hp1.y = h3;
            __nv_bfloat162 lp0 = __floats2bfloat162_rn(v.x - __bfloat162float(h0),
                                                       v.y - __bfloat162float(h1));
            __nv_bfloat162 lp1 = __floats2bfloat162_rn(v.z - __bfloat162float(h2),
                                                       v.w - __bfloat162float(h3));
            uint64_t hi64 = (uint64_t)(*(uint32_t*)&hp0) | ((uint64_t)(*(uint32_t*)&hp1) << 32);
            uint64_t lo64 = (uint64_t)(*(uint32_t*)&lp0) | ((uint64_t)(*(uint32_t*)&lp1) << 32);
            uint32_t so = SWZ((uint32_t)(r * 128 + half * 64 + i * 8));
            *(uint64_t*)(smem + so) = hi64;
            *(uint64_t*)(smem + 16384 + so) = lo64;
        }
        // ---- B chunk: bf16 copy, store swizzled ----
#pragma unroll
        for (int j = 0; j < 4; j++) {
            uint4 bh = *(const uint4*)(bhp + kc * 64 + j * 8);
            uint4 blv = *(const uint4*)(blp + kc * 64 + j * 8);
            uint32_t so = SWZ((uint32_t)(r * 128 + half * 64 + j * 16));
            *(uint4*)(smem + 32768 + so) = bh;
            *(uint4*)(smem + 49152 + so) = blv;
        }
        __syncthreads();

        // ---- compute: 4 k16 steps ----
#pragma unroll
        for (int ks = 0; ks < 4; ks++) {
            // B fragments for 4 n-atoms (hi & lo) — NON-trans: tile is [n][k]
            uint32_t bh_[4][2], bl_[4][2];
#pragma unroll
            for (int na = 0; na < 4; na++) {
                uint32_t o = (uint32_t)((wn + na * 8 + (lane & 7)) * 128);
                uint32_t seg = (uint32_t)((ks * 2 + ((lane >> 3) & 1)) * 16);
                uint32_t ad = o + (seg ^ ((o >> 3) & 0x70));
                ldm_x2(bh_[na], sB_hi + ad);
                ldm_x2(bl_[na], sB_lo + ad);
            }
#pragma unroll
            for (int ma = 0; ma < 4; ma++) {
                uint32_t o = (uint32_t)((wm + ma * 16 + (lane & 15)) * 128);
                uint32_t seg = (uint32_t)((ks * 2 + (lane >> 4)) * 16);
                uint32_t ad = o + (seg ^ ((o >> 3) & 0x70));
                uint32_t ah[4], al[4];
                ldm_x4(ah, sA_hi + ad);
                ldm_x4(al, sA_lo + ad);
#pragma unroll
                for (int na = 0; na < 4; na++) {
                    mma16816(acc[ma][na], ah, bh_[na]);
                    mma16816(acc[ma][na], ah, bl_[na]);
                    mma16816(acc[ma][na], al, bh_[na]);
                }
            }
        }
    }

    // ---- epilogue ----
    const int quad = lane >> 2, qt = lane & 3;
    const bool isR = (col0 >= 256);
    float* __restrict__ out = isR ? g_yr : g_yl;
#pragma unroll
    for (int ma = 0; ma < 4; ma++) {
#pragma unroll
        for (int na = 0; na < 4; na++) {
            int cl = (col0 + wn + na * 8 + qt * 2) & 255;
            float b0 = 0.f, b1 = 0.f;
            if (isR) { b0 = bl[cl]; b1 = bl[cl + 1]; }
            int row = m0 + wm + ma * 16 + quad;
            float2 v0; v0.x = acc[ma][na][0] + b0; v0.y = acc[ma][na][1] + b1;
            float2 v1; v1.x = acc[ma][na][2] + b0; v1.y = acc[ma][na][3] + b1;
            *(float2*)(out + (size_t)row * FF + cl)       = v0;
            *(float2*)(out + (size_t)(row + 8) * FF + cl) = v1;
        }
    }
}

// ================= SAGE combine (CSR gather) =================
__global__ __launch_bounds__(256) void k_sage(int dstA) {
    float* __restrict__ out = dstA ? g_bufA : g_bufB;
    int n = blockIdx.x;
    int j = threadIdx.x;
    int e0 = g_rowptr[n], e1 = g_rowptr[n + 1];
    float inv = g_invdeg[n];

    float sacc[CC];
#pragma unroll
    for (int c = 0; c < CC; c++) sacc[c] = 0.f;

    __shared__ int sc[64];
    for (int eb = e0; eb < e1; eb += 64) {
        int m = min(64, e1 - eb);
        __syncthreads();
        if (j < m) sc[j] = g_colidx[eb + j];
        __syncthreads();
        for (int q = 0; q < m; q++) {
            int src = sc[q];
            const float* p = g_yl + (size_t)src * FF + j;
#pragma unroll
            for (int c = 0; c < CC; c++)
                sacc[c] += p[(size_t)c * NN * FF];
        }
    }
#pragma unroll
    for (int c = 0; c < CC; c++) {
        size_t o = ((size_t)c * NN + n) * FF + j;
        out[o] = fmaxf(sacc[c] * inv + g_yr[o], 0.f);
    }
}

__global__ void k_pool() {
    int c = blockIdx.x, chunk = blockIdx.y, j = threadIdx.x;
    int n0 = chunk * 250;
    float acc = 0.f;
    for (int n = n0; n < n0 + 250; n++)
        acc += g_bufA[((size_t)c * NN + n) * FF + j];
    atomicAdd(&g_pool[c * FF + j], acc);
}

__global__ __launch_bounds__(256) void k_mlp(
    const float* __restrict__ w1, const float* __restrict__ b1,
    const float* __restrict__ w2, const float* __restrict__ b2,
    const float* __restrict__ w3, const float* __restrict__ b3,
    float* __restrict__ outp)
{
    __shared__ float g[CC][FF];
    __shared__ float h[CC][FF];
    int j = threadIdx.x;
    const float scale = 1.0f / (float)NN;
#pragma unroll
    for (int c = 0; c < CC; c++) g[c][j] = g_pool[c * FF + j] * scale;
    __syncthreads();
    {
        float accs[CC];
#pragma unroll
        for (int c = 0; c < CC; c++) accs[c] = 0.f;
        for (int k = 0; k < FF; k++) {
            float wv = w1[k * FF + j];
#pragma unroll
            for (int c = 0; c < CC; c++) accs[c] += g[c][k] * wv;
        }
        float bb = b1[j];
#pragma unroll
        for (int c = 0; c < CC; c++) h[c][j] = fmaxf(accs[c] + bb, 0.f);
    }
    __syncthreads();
    {
        float accs[CC];
#pragma unroll
        for (int c = 0; c < CC; c++) accs[c] = 0.f;
        for (int k = 0; k < FF; k++) {
            float wv = w2[k * FF + j];
#pragma unroll
            for (int c = 0; c < CC; c++) accs[c] += h[c][k] * wv;
        }
        float bb = b2[j];
#pragma unroll
        for (int c = 0; c < CC; c++) g[c][j] = fmaxf(accs[c] + bb, 0.f);
    }
    __syncthreads();
    {
        float wv = w3[j];
#pragma unroll
        for (int c = 0; c < CC; c++) h[c][j] = g[c][j] * wv;
        __syncthreads();
        if (j < CC) {
            float s = 0.f;
            for (int k = 0; k < FF; k++) s += h[j][k];
            outp[j] = s + b3[0];
        }
    }
}

// ---------------------------------------------------------------------
extern "C" void kernel_launch(void* const* d_in, const int* in_sizes, int n_in,
                              void* d_out, int out_size) {
    const int*   x_node_cfg = (const int*)  d_in[0];
    const float* x_feat     = (const float*)d_in[1];
    const int*   x_op       = (const int*)  d_in[2];
    const int*   edge_index = (const int*)  d_in[3];
    const float* emb_op     = (const float*)d_in[4];
    const float* emb_layout = (const float*)d_in[5];
    const float* lin_w      = (const float*)d_in[6];
    const float* lin_b      = (const float*)d_in[7];
    const float* conv_wl    = (const float*)d_in[8];
    const float* conv_bl    = (const float*)d_in[9];
    const float* conv_wr    = (const float*)d_in[10];
    const float* w1         = (const float*)d_in[11];
    const float* b1         = (const float*)d_in[12];
    const float* w2         = (const float*)d_in[13];
    const float* b2         = (const float*)d_in[14];
    const float* w3         = (const float*)d_in[15];
    const float* b3         = (const float*)d_in[16];
    float* outp = (float*)d_out;

    cudaFuncSetAttribute(k_gemm_mma, cudaFuncAttributeMaxDynamicSharedMemorySize, 65536);

    k_table<<<CFGF * 8, FF>>>(emb_layout, lin_w);
    k_small_zero<<<(NN + 255) / 256, 256>>>();
    k_deg_acc<<<(EE + 255) / 256, 256>>>(edge_index);
    k_scan<<<1, 256>>>();
    k_fill<<<(EE + 255) / 256, 256>>>(edge_index);
    k_base<<<NN, FF>>>(x_feat, x_op, emb_op, lin_w, lin_b);
    k_initx<<<dim3(NN, CC), FF>>>(x_node_cfg);
    k_wsplit<<<(4 * 512 * 256) / 256, 256>>>(conv_wl, conv_wr);

    for (int i = 0; i < 4; i++) {
        int srcA = (i % 2 == 0) ? 1 : 0;
        k_gemm_mma<<<dim3(4, (CC * NN) / 128), 256, 65536>>>(
            srcA, i, conv_bl + (size_t)i * FF);
        k_sage<<<NN, FF>>>(srcA ? 0 : 1);
    }

    k_pool<<<dim3(CC, NN / 250), FF>>>();
    k_mlp<<<1, FF>>>(w1, b1, w2, b2, w3, b3, outp);
}

// round 7
// speedup vs baseline: 1.8323x; 1.2095x over previous
#include <cuda_runtime.h>
#include <cuda_bf16.h>
#include <cstdint>

#define CC 16
#define NN 10000
#define EE 40000
#define FF 256
#define CFGF 18

// ---- scratch (static __device__ arrays; no allocations anywhere) ----
__device__ float g_bufA[CC * NN * FF];   // ping (x)
__device__ float g_bufB[CC * NN * FF];   // pong (x)
__device__ float g_yl [CC * NN * FF];    // x @ wl
__device__ float g_yr [CC * NN * FF];    // x @ wr + bl
__device__ float g_base[NN * FF];
__device__ float g_T   [CFGF * 8 * FF];
__device__ float g_invdeg[NN];
__device__ float g_pool[CC * FF];
__device__ int   g_deg[NN];
__device__ int   g_cursor[NN];
__device__ int   g_rowptr[NN + 1];
__device__ int   g_colidx[EE];
__device__ __nv_bfloat16 g_whi[4 * 512 * 256];  // weights split hi, [layer][n][k]
__device__ __nv_bfloat16 g_wlo[4 * 512 * 256];  // weights split lo

// ================= helpers =================
#define SWZ(o) ((o) ^ (((o) >> 3) & 0x70))

__device__ __forceinline__ uint32_t s2u(const void* p) {
    uint32_t a;
    asm("{ .reg .u64 t; cvta.to.shared.u64 t, %1; cvt.u32.u64 %0, t; }"
        : "=r"(a) : "l"(p));
    return a;
}
__device__ __forceinline__ void ldm_x4(uint32_t* r, uint32_t addr) {
    asm volatile("ldmatrix.sync.aligned.m8n8.x4.shared.b16 {%0,%1,%2,%3}, [%4];"
                 : "=r"(r[0]), "=r"(r[1]), "=r"(r[2]), "=r"(r[3]) : "r"(addr));
}
__device__ __forceinline__ void ldm_x2(uint32_t* r, uint32_t addr) {
    asm volatile("ldmatrix.sync.aligned.m8n8.x2.shared.b16 {%0,%1}, [%2];"
                 : "=r"(r[0]), "=r"(r[1]) : "r"(addr));
}
__device__ __forceinline__ void mma16816(float* d, const uint32_t* a, const uint32_t* b) {
    asm volatile(
        "mma.sync.aligned.m16n8k16.row.col.f32.bf16.bf16.f32 "
        "{%0,%1,%2,%3}, {%4,%5,%6,%7}, {%8,%9}, {%0,%1,%2,%3};"
        : "+f"(d[0]), "+f"(d[1]), "+f"(d[2]), "+f"(d[3])
        : "r"(a[0]), "r"(a[1]), "r"(a[2]), "r"(a[3]), "r"(b[0]), "r"(b[1]));
}
__device__ __forceinline__ void cp16(uint32_t saddr, const void* gptr) {
    asm volatile("cp.async.ca.shared.global [%0], [%1], 16;"
                 :: "r"(saddr), "l"(gptr) : "memory");
}

// ================= prologue kernels =================
// blocks [0,144): T table;  blocks [144, 144+NN): base
__global__ void k_tablebase(const float* __restrict__ emb_layout,
                            const float* __restrict__ lin_w,
                            const float* __restrict__ lin_b,
                            const float* __restrict__ x_feat,
                            const int*   __restrict__ x_op,
                            const float* __restrict__ emb_op) {
    int j = threadIdx.x;
    if (blockIdx.x < 144) {
        int blk = blockIdx.x;
        int k = blk >> 3, v = blk & 7;
        float acc = 0.f;
#pragma unroll
        for (int d = 0; d < 4; d++)
            acc += emb_layout[v * 4 + d] * lin_w[(140 + k * 4 + d) * FF + j];
        g_T[blk * FF + j] = acc;
        return;
    }
    int n = blockIdx.x - 144;
    __shared__ float sf[144];
    if (j < 140) sf[j] = x_feat[n * 140 + j];
    if (j >= 140 && j < 144) {
        int op = x_op[n];
        sf[j] = emb_op[op * 4 + (j - 140)];
    }
    __syncthreads();
    float acc = lin_b[j];
#pragma unroll 4
    for (int d = 0; d < 140; d++) acc += sf[d] * lin_w[d * FF + j];
#pragma unroll
    for (int d = 0; d < 4; d++)   acc += sf[140 + d] * lin_w[(212 + d) * FF + j];
    g_base[n * FF + j] = acc;
}

__global__ void k_small_zero() {
    int i = blockIdx.x * blockDim.x + threadIdx.x;
    if (i < NN) { g_deg[i] = 0; g_cursor[i] = 0; }
    if (i < CC * FF) g_pool[i] = 0.f;
}
__global__ void k_deg_acc(const int* __restrict__ edge_index) {
    int e = blockIdx.x * blockDim.x + threadIdx.x;
    if (e < EE) atomicAdd(&g_deg[edge_index[EE + e]], 1);
}
__global__ void k_scan() {
    __shared__ int csum[256];
    int t = threadIdx.x;
    const int CH = (NN + 255) / 256;  // 40
    int base = t * CH;
    int s = 0;
    for (int i = 0; i < CH; i++) {
        int idx = base + i;
        if (idx < NN) s += g_deg[idx];
    }
    csum[t] = s;
    __syncthreads();
    if (t == 0) {
        int acc = 0;
        for (int i = 0; i < 256; i++) { int v = csum[i]; csum[i] = acc; acc += v; }
        g_rowptr[NN] = acc;
    }
    __syncthreads();
    int acc = csum[t];
    for (int i = 0; i < CH; i++) {
        int idx = base + i;
        if (idx < NN) {
            g_rowptr[idx] = acc;
            int d = g_deg[idx];
            acc += d;
            g_invdeg[idx] = 1.0f / fmaxf((float)d, 1.0f);
        }
    }
}
__global__ void k_fill(const int* __restrict__ edge_index) {
    int e = blockIdx.x * blockDim.x + threadIdx.x;
    if (e < EE) {
        int dst = edge_index[EE + e];
        int p = atomicAdd(&g_cursor[dst], 1);
        g_colidx[g_rowptr[dst] + p] = edge_index[e];
    }
}

__global__ void k_initx(const int* __restrict__ x_node_cfg) {
    int n = blockIdx.x, c = blockIdx.y, j = threadIdx.x;
    __shared__ int scfg[CFGF];
    if (j < CFGF) scfg[j] = x_node_cfg[((size_t)c * NN + n) * CFGF + j];
    __syncthreads();
    float acc = g_base[n * FF + j];
#pragma unroll
    for (int k = 0; k < CFGF; k++)
        acc += g_T[(k * 8 + scfg[k]) * FF + j];
    g_bufA[((size_t)c * NN + n) * FF + j] = acc;
}

// split all 4 layers' weights into bf16 hi/lo in [layer][n(512)][k(256)] layout
__global__ void k_wsplit(const float* __restrict__ conv_wl,
                         const float* __restrict__ conv_wr) {
    int t = blockIdx.x * 256 + threadIdx.x;   // 0 .. 4*512*256-1
    int l = t >> 17;
    int rem = t & 131071;
    int n = rem >> 8, k = rem & 255;
    const float* w = (n < 256) ? (conv_wl + (size_t)l * 65536)
                               : (conv_wr + (size_t)l * 65536);
    float v = w[k * 256 + (n & 255)];
    __nv_bfloat16 h = __float2bfloat16(v);
    g_whi[t] = h;
    g_wlo[t] = __float2bfloat16(v - __bfloat162float(h));
}

// ================= HMMA bf16x3 GEMM (pipelined) =================
// y = x @ [wl | wr]  (M=160000, K=256, N=512)
// CTA 128x128; grid (4 col tiles, 1250 row tiles); 8 warps: 2(m) x 4(n)
// smem: A_hi 16K | A_lo 16K | Bstage0 (hi16K lo16K) | Bstage1 (hi16K lo16K) = 96KB
// A: register prefetch + convert; B: cp.async double buffer.
#define SMB(stage) (32768 + (stage) * 32768)
__global__ __launch_bounds__(256, 2) void k_gemm_mma(int srcA, int layer,
                                                     const float* __restrict__ bl) {
    extern __shared__ __align__(128) char smem[];
    const float* __restrict__ x = srcA ? g_bufA : g_bufB;

    const int tid = threadIdx.x;
    const int wid = tid >> 5, lane = tid & 31;
    const int col0 = blockIdx.x * 128;
    const int m0 = blockIdx.y * 128;
    const int wm = (wid & 1) * 64;       // warp m base
    const int wn = (wid >> 1) * 32;      // warp n base

    const uint32_t sbase = s2u(smem);
    const uint32_t sA_hi = sbase;
    const uint32_t sA_lo = sbase + 16384;

    float acc[4][4][4];
#pragma unroll
    for (int i = 0; i < 4; i++)
#pragma unroll
        for (int j = 0; j < 4; j++)
#pragma unroll
            for (int q = 0; q < 4; q++) acc[i][j][q] = 0.f;

    const int r = tid >> 1, half = tid & 1;
    const float* ap = x + (size_t)(m0 + r) * FF + half * 32;
    const __nv_bfloat16* bhp = g_whi + ((size_t)(layer * 512 + col0 + r) << 8) + half * 32;
    const __nv_bfloat16* blp = g_wlo + ((size_t)(layer * 512 + col0 + r) << 8) + half * 32;
    const uint32_t bso = SWZ((uint32_t)(r * 128 + half * 64));  // j=0 swizzled base pattern varies per j; compute per j below

    // ---- prologue: B chunk 0 via cp.async; A chunk 0 into regs ----
#pragma unroll
    for (int j = 0; j < 4; j++) {
        uint32_t so = SWZ((uint32_t)(r * 128 + half * 64 + j * 16));
        cp16(sbase + SMB(0) + so,         bhp + j * 8);
        cp16(sbase + SMB(0) + 16384 + so, blp + j * 8);
    }
    asm volatile("cp.async.commit_group;" ::: "memory");
    float4 areg[8];
#pragma unroll
    for (int i = 0; i < 8; i++) areg[i] = *(const float4*)(ap + i * 4);
    (void)bso;

#pragma unroll
    for (int kc = 0; kc < 4; kc++) {
        __syncthreads();   // previous compute done reading A smem
        // ---- convert & store A chunk kc from regs ----
#pragma unroll
        for (int i = 0; i < 8; i++) {
            float4 v = areg[i];
            __nv_bfloat16 h0 = __float2bfloat16(v.x), h1 = __float2bfloat16(v.y),
                          h2 = __float2bfloat16(v.z), h3 = __float2bfloat16(v.w);
            __nv_bfloat162 hp0; hp0.x = h0; hp0.y = h1;
            __nv_bfloat162 hp1; hp1.x = h2; hp1.y = h3;
            __nv_bfloat162 lp0 = __floats2bfloat162_rn(v.x - __bfloat162float(h0),
                                                       v.y - __bfloat162float(h1));
            __nv_bfloat162 lp1 = __floats2bfloat162_rn(v.z - __bfloat162float(h2),
                                                       v.w - __bfloat162float(h3));
            uint64_t hi64 = (uint64_t)(*(uint32_t*)&hp0) | ((uint64_t)(*(uint32_t*)&hp1) << 32);
            uint64_t lo64 = (uint64_t)(*(uint32_t*)&lp0) | ((uint64_t)(*(uint32_t*)&lp1) << 32);
            uint32_t so = SWZ((uint32_t)(r * 128 + half * 64 + i * 8));
            *(uint64_t*)(smem + so) = hi64;
            *(uint64_t*)(smem + 16384 + so) = lo64;
        }
        // ---- issue next B stage ----
        if (kc < 3) {
#pragma unroll
            for (int j = 0; j < 4; j++) {
                uint32_t so = SWZ((uint32_t)(r * 128 + half * 64 + j * 16));
                cp16(sbase + SMB((kc + 1) & 1) + so,         bhp + (kc + 1) * 64 + j * 8);
                cp16(sbase + SMB((kc + 1) & 1) + 16384 + so, blp + (kc + 1) * 64 + j * 8);
            }
            asm volatile("cp.async.commit_group;" ::: "memory");
            asm volatile("cp.async.wait_group 1;" ::: "memory");
        } else {
            asm volatile("cp.async.wait_group 0;" ::: "memory");
        }
        __syncthreads();
        // ---- prefetch next A chunk into regs (overlaps compute) ----
        if (kc < 3) {
#pragma unroll
            for (int i = 0; i < 8; i++)
                areg[i] = *(const float4*)(ap + (kc + 1) * 64 + i * 4);
        }

        const uint32_t sB_hi = sbase + SMB(kc & 1);
        const uint32_t sB_lo = sB_hi + 16384;
        // ---- compute: 4 k16 steps ----
#pragma unroll
        for (int ks = 0; ks < 4; ks++) {
            uint32_t bh_[4][2], bl_[4][2];
#pragma unroll
            for (int na = 0; na < 4; na++) {
                uint32_t o = (uint32_t)((wn + na * 8 + (lane & 7)) * 128);
                uint32_t seg = (uint32_t)((ks * 2 + ((lane >> 3) & 1)) * 16);
                uint32_t ad = o + (seg ^ ((o >> 3) & 0x70));
                ldm_x2(bh_[na], sB_hi + ad);
                ldm_x2(bl_[na], sB_lo + ad);
            }
#pragma unroll
            for (int ma = 0; ma < 4; ma++) {
                uint32_t o = (uint32_t)((wm + ma * 16 + (lane & 15)) * 128);
                uint32_t seg = (uint32_t)((ks * 2 + (lane >> 4)) * 16);
                uint32_t ad = o + (seg ^ ((o >> 3) & 0x70));
                uint32_t ah[4], al[4];
                ldm_x4(ah, sA_hi + ad);
                ldm_x4(al, sA_lo + ad);
#pragma unroll
                for (int na = 0; na < 4; na++) {
                    mma16816(acc[ma][na], ah, bh_[na]);
                    mma16816(acc[ma][na], ah, bl_[na]);
                    mma16816(acc[ma][na], al, bh_[na]);
                }
            }
        }
    }

    // ---- epilogue ----
    const int quad = lane >> 2, qt = lane & 3;
    const bool isR = (col0 >= 256);
    float* __restrict__ out = isR ? g_yr : g_yl;
#pragma unroll
    for (int ma = 0; ma < 4; ma++) {
#pragma unroll
        for (int na = 0; na < 4; na++) {
            int cl = (col0 + wn + na * 8 + qt * 2) & 255;
            float b0 = 0.f, b1 = 0.f;
            if (isR) { b0 = bl[cl]; b1 = bl[cl + 1]; }
            int row = m0 + wm + ma * 16 + quad;
            float2 v0; v0.x = acc[ma][na][0] + b0; v0.y = acc[ma][na][1] + b1;
            float2 v1; v1.x = acc[ma][na][2] + b0; v1.y = acc[ma][na][3] + b1;
            *(float2*)(out + (size_t)row * FF + cl)       = v0;
            *(float2*)(out + (size_t)(row + 8) * FF + cl) = v1;
        }
    }
}

// ================= SAGE combine (CSR gather) =================
__global__ __launch_bounds__(256) void k_sage(int dstA) {
    float* __restrict__ out = dstA ? g_bufA : g_bufB;
    int n = blockIdx.x;
    int j = threadIdx.x;
    int e0 = g_rowptr[n], e1 = g_rowptr[n + 1];
    float inv = g_invdeg[n];

    // preload yr (16 independent loads overlap the gather chain)
    float yrv[CC];
#pragma unroll
    for (int c = 0; c < CC; c++)
        yrv[c] = g_yr[((size_t)c * NN + n) * FF + j];

    float sacc[CC];
#pragma unroll
    for (int c = 0; c < CC; c++) sacc[c] = 0.f;

    __shared__ int sc[64];
    for (int eb = e0; eb < e1; eb += 64) {
        int m = min(64, e1 - eb);
        __syncthreads();
        if (j < m) sc[j] = g_colidx[eb + j];
        __syncthreads();
        for (int q = 0; q < m; q++) {
            int src = sc[q];
            const float* p = g_yl + (size_t)src * FF + j;
#pragma unroll
            for (int c = 0; c < CC; c++)
                sacc[c] += p[(size_t)c * NN * FF];
        }
    }
#pragma unroll
    for (int c = 0; c < CC; c++) {
        size_t o = ((size_t)c * NN + n) * FF + j;
        out[o] = fmaxf(sacc[c] * inv + yrv[c], 0.f);
    }
}

__global__ void k_pool() {
    int c = blockIdx.x, chunk = blockIdx.y, j = threadIdx.x;
    int n0 = chunk * 250;
    float acc = 0.f;
    for (int n = n0; n < n0 + 250; n++)
        acc += g_bufA[((size_t)c * NN + n) * FF + j];
    atomicAdd(&g_pool[c * FF + j], acc);
}

__global__ __launch_bounds__(256) void k_mlp(
    const float* __restrict__ w1, const float* __restrict__ b1,
    const float* __restrict__ w2, const float* __restrict__ b2,
    const float* __restrict__ w3, const float* __restrict__ b3,
    float* __restrict__ outp)
{
    __shared__ float g[CC][FF];
    __shared__ float h[CC][FF];
    int j = threadIdx.x;
    const float scale = 1.0f / (float)NN;
#pragma unroll
    for (int c = 0; c < CC; c++) g[c][j] = g_pool[c * FF + j] * scale;
    __syncthreads();
    {
        float accs[CC];
#pragma unroll
        for (int c = 0; c < CC; c++) accs[c] = 0.f;
        for (int k = 0; k < FF; k++) {
            float wv = w1[k * FF + j];
#pragma unroll
            for (int c = 0; c < CC; c++) accs[c] += g[c][k] * wv;
        }
        float bb = b1[j];
#pragma unroll
        for (int c = 0; c < CC; c++) h[c][j] = fmaxf(accs[c] + bb, 0.f);
    }
    __syncthreads();
    {
        float accs[CC];
#pragma unroll
        for (int c = 0; c < CC; c++) accs[c] = 0.f;
        for (int k = 0; k < FF; k++) {
            float wv = w2[k * FF + j];
#pragma unroll
            for (int c = 0; c < CC; c++) accs[c] += h[c][k] * wv;
        }
        float bb = b2[j];
#pragma unroll
        for (int c = 0; c < CC; c++) g[c][j] = fmaxf(accs[c] + bb, 0.f);
    }
    __syncthreads();
    {
        float wv = w3[j];
#pragma unroll
        for (int c = 0; c < CC; c++) h[c][j] = g[c][j] * wv;
        __syncthreads();
        if (j < CC) {
            float s = 0.f;
            for (int k = 0; k < FF; k++) s += h[j][k];
            outp[j] = s + b3[0];
        }
    }
}

// ---------------------------------------------------------------------
extern "C" void kernel_launch(void* const* d_in, const int* in_sizes, int n_in,
                              void* d_out, int out_size) {
    const int*   x_node_cfg = (const int*)  d_in[0];
    const float* x_feat     = (const float*)d_in[1];
    const int*   x_op       = (const int*)  d_in[2];
    const int*   edge_index = (const int*)  d_in[3];
    const float* emb_op     = (const float*)d_in[4];
    const float* emb_layout = (const float*)d_in[5];
    const float* lin_w      = (const float*)d_in[6];
    const float* lin_b      = (const float*)d_in[7];
    const float* conv_wl    = (const float*)d_in[8];
    const float* conv_bl    = (const float*)d_in[9];
    const float* conv_wr    = (const float*)d_in[10];
    const float* w1         = (const float*)d_in[11];
    const float* b1         = (const float*)d_in[12];
    const float* w2         = (const float*)d_in[13];
    const float* b2         = (const float*)d_in[14];
    const float* w3         = (const float*)d_in[15];
    const float* b3         = (const float*)d_in[16];
    float* outp = (float*)d_out;

    cudaFuncSetAttribute(k_gemm_mma, cudaFuncAttributeMaxDynamicSharedMemorySize, 98304);

    // launch order: gemm layer 0 lands at profiled slot (index 3)
    k_wsplit<<<(4 * 512 * 256) / 256, 256>>>(conv_wl, conv_wr);            // 0
    k_tablebase<<<144 + NN, FF>>>(emb_layout, lin_w, lin_b,
                                  x_feat, x_op, emb_op);                    // 1
    k_initx<<<dim3(NN, CC), FF>>>(x_node_cfg);                              // 2
    k_gemm_mma<<<dim3(4, (CC * NN) / 128), 256, 98304>>>(
        1, 0, conv_bl);                                                     // 3 (profiled)

    // CSR build (only needed by k_sage)
    k_small_zero<<<(NN + 255) / 256, 256>>>();                              // 4
    k_deg_acc<<<(EE + 255) / 256, 256>>>(edge_index);                       // 5
    k_scan<<<1, 256>>>();                                                   // 6
    k_fill<<<(EE + 255) / 256, 256>>>(edge_index);                          // 7
    k_sage<<<NN, FF>>>(0);                                                  // 8: layer0 -> bufB

    for (int i = 1; i < 4; i++) {
        int srcA = (i % 2 == 0) ? 1 : 0;
        k_gemm_mma<<<dim3(4, (CC * NN) / 128), 256, 98304>>>(
            srcA, i, conv_bl + (size_t)i * FF);
        k_sage<<<NN, FF>>>(srcA ? 0 : 1);
    }

    k_pool<<<dim3(CC, NN / 250), FF>>>();
    k_mlp<<<1, FF>>>(w1, b1, w2, b2, w3, b3, outp);
}